// round 11
// baseline (speedup 1.0000x reference)
#include <cuda_runtime.h>
#include <cuda_bf16.h>
#include <math.h>

// AUCM pairwise margin loss, B=1024, C=128, margin=1. One launch.
//
// Math: softplus(b-a), a,b = sigmoids in (0,1), t = b-a in (-1,1):
//   softplus(t) = ln2 + t/2 + t^2/8 - t^4/192 + t^6/2880  (+O(t^8), <2.6e-5 abs)
// Binomial factorization collapses the O(B^2) (pos,neg) pair sum per class to
// 7 power-sum moments of pos probs and 7 of all probs (neg = all - pos).
//
// R11: cut the L1-wavefront floor. Block = (4 adjacent classes) x (256-row
// quarter): lanes span 4 classes sharing each 128B line -> 8 lines/request
// instead of 32; footprint 256 rows x 2 arrays -> 512 wavefronts/SM (was
// 2048). 32 class-groups x 4 row-quarters = 128 blocks (full wave).
// Cross-block combine uses the R8-proven zero-contention path: plain STGs of
// raw partial moments to distinct addresses + fence + one ticket ATOMG; the
// last block's 128 threads reload 4x14 values each (parallel, MLP=56), do
// the fp32 binomial combine (one class per thread), reduce, store, reset.

#define NROWS 1024
#define NCLS  128
#define NBLK  128
#define NTH   128
#define NQ    4                   // row quarters
#define CPB   4                   // classes per block
#define NGRP  (NCLS / CPB)        // 32 class groups
#define RPQ   (NROWS / NQ)        // 256 rows per block
#define RPT   (RPQ / (NTH / CPB)) // 8 rows per thread
#define NM    7                   // moments k = 0..6
#define NW    (NTH / 32)          // 4 warps

__device__ float g_part[NQ][NCLS][2 * NM];   // raw partial moments
__device__ unsigned int g_count = 0;

__global__ __launch_bounds__(NTH)
void aucm_kernel(const float* __restrict__ logits,
                 const float* __restrict__ targets,
                 float* __restrict__ out)
{
    const int b    = blockIdx.x;
    const int g    = b & (NGRP - 1);     // class group -> classes [4g, 4g+4)
    const int q    = b >> 5;             // row quarter
    const int tid  = threadIdx.x;
    const int cs   = tid & (CPB - 1);    // class within group
    const int rt   = tid >> 2;           // row-thread 0..31
    const int warp = tid >> 5;
    const int c    = g * CPB + cs;

    // T[k] = sum over my rows of p^k; P[k] = same restricted to pos rows.
    float T[NM], P[NM];
#pragma unroll
    for (int k = 0; k < NM; k++) { T[k] = 0.0f; P[k] = 0.0f; }

    const int row0 = q * RPQ + rt;
#pragma unroll
    for (int r = 0; r < RPT; r++) {
        const int   row = row0 + r * 32;
        const float x   = logits[row * NCLS + c];   // 8 lines/warp-request
        const float tg  = targets[row * NCLS + c];  // exact 0.0f / 1.0f
        const float p   = __fdividef(1.0f, 1.0f + __expf(-x));
        float pw = 1.0f;
#pragma unroll
        for (int k = 0; k < NM; k++) {
            T[k] += pw;
            P[k] = fmaf(tg, pw, P[k]);
            pw *= p;
        }
    }

    // Reduce over row-threads within the warp (keep 4 classes separate):
    // rt occupies lane bits [2:5) -> xor offsets 4, 8, 16.
#pragma unroll
    for (int off = 4; off <= 16; off <<= 1) {
#pragma unroll
        for (int k = 0; k < NM; k++) {
            T[k] += __shfl_xor_sync(0xffffffffu, T[k], off);
            P[k] += __shfl_xor_sync(0xffffffffu, P[k], off);
        }
    }

    __shared__ float sT[NW][CPB][NM];
    __shared__ float sP[NW][CPB][NM];
    __shared__ unsigned int s_ticket;
    if ((tid & 31) < CPB) {
#pragma unroll
        for (int k = 0; k < NM; k++) {
            sT[warp][tid & 31][k] = T[k];
            sP[warp][tid & 31][k] = P[k];
        }
    }
    __syncthreads();

    // 56 threads: one (class, moment) each; sum 4 warps, publish raw partial.
    if (tid < CPB * 2 * NM) {
        const int cls = tid / (2 * NM);        // 0..3
        const int m   = tid % (2 * NM);        // 0..13
        const int k   = (m < NM) ? m : (m - NM);
        const float* s = (m < NM) ? &sT[0][cls][k] : &sP[0][cls][k];
        float v = 0.0f;
#pragma unroll
        for (int w = 0; w < NW; w++) v += s[w * CPB * NM];
        g_part[q][g * CPB + cls][m] = v;       // distinct address, plain STG
        __threadfence();                       // publish before my ticket
    }
    __syncthreads();
    if (tid == 0) s_ticket = atomicAdd(&g_count, 1u);
    __syncthreads();
    if (s_ticket != (unsigned)(NBLK - 1)) return;

    // ---- last block: parallel fp32 finalize, one class per thread ----
    __threadfence();     // acquire side
    float Td[NM], Pd[NM];
#pragma unroll
    for (int k = 0; k < NM; k++) {
        float a = 0.0f, p2 = 0.0f;
#pragma unroll
        for (int qq = 0; qq < NQ; qq++) {
            a  += *(volatile float*)&g_part[qq][tid][k];
            p2 += *(volatile float*)&g_part[qq][tid][NM + k];
        }
        Td[k] = a; Pd[k] = p2;
    }
    float Bd[NM], Am[NM];
#pragma unroll
    for (int k = 0; k < NM; k++) {
        Bd[k] = Td[k] - Pd[k];                 // neg moments
        Am[k] = (k & 1) ? -Pd[k] : Pd[k];      // sum over pos of (-a)^k
    }
    const float cnt = Pd[0] * Bd[0];

    const float C2[3] = {1, 2, 1};
    const float C4[5] = {1, 4, 6, 4, 1};
    const float C6[7] = {1, 6, 15, 20, 15, 6, 1};
    const float d1 = Bd[1] * Am[0] + Bd[0] * Am[1];
    float d2 = 0.0f, d4 = 0.0f, d6 = 0.0f;
#pragma unroll
    for (int r = 0; r <= 2; r++) d2 += C2[r] * Bd[r] * Am[2 - r];
#pragma unroll
    for (int r = 0; r <= 4; r++) d4 += C4[r] * Bd[r] * Am[4 - r];
#pragma unroll
    for (int r = 0; r <= 6; r++) d6 += C6[r] * Bd[r] * Am[6 - r];

    const float S = 0.6931472f * cnt
                  + 0.5f * d1
                  + d2 * (1.0f / 8.0f)
                  - d4 * (1.0f / 192.0f)
                  + d6 * (1.0f / 2880.0f);

    float mean = 0.0f, vd = 0.0f;
    if (cnt > 0.0f) { mean = S / cnt; vd = 1.0f; }

    // 128 -> 1 reduction.
#pragma unroll
    for (int off = 16; off > 0; off >>= 1) {
        mean += __shfl_xor_sync(0xffffffffu, mean, off);
        vd   += __shfl_xor_sync(0xffffffffu, vd,   off);
    }
    __shared__ float rm[NW], rv[NW];
    if ((tid & 31) == 0) { rm[warp] = mean; rv[warp] = vd; }
    __syncthreads();
    if (tid == 0) {
        float sm = 0.0f, sv = 0.0f;
#pragma unroll
        for (int w = 0; w < NW; w++) { sm += rm[w]; sv += rv[w]; }
        out[0] = (sv > 0.0f) ? (sm / sv) : 0.0f;
        g_count = 0;     // reset ticket for next graph replay
    }
    // g_part is plain-overwritten every replay -> deterministic, no reset.
}

extern "C" void kernel_launch(void* const* d_in, const int* in_sizes, int n_in,
                              void* d_out, int out_size)
{
    const float* logits  = (const float*)d_in[0];
    const float* targets = (const float*)d_in[1];
    float* out = (float*)d_out;

    aucm_kernel<<<NBLK, NTH>>>(logits, targets, out);
}

// round 12
// speedup vs baseline: 1.1845x; 1.1845x over previous
#include <cuda_runtime.h>
#include <cuda_bf16.h>
#include <math.h>

// AUCM pairwise margin loss, B=1024, C=128, margin=1. One launch.
//
// Math: softplus(b-a), a,b = sigmoids in (0,1), t = b-a in (-1,1):
//   softplus(t) = ln2 + t/2 + t^2/8 - t^4/192   (degree-4; truncation
//   worst-case <3.5e-4 abs, ~1.5e-5 realistic; gate is 1e-3)
// Binomial factorization collapses the O(B^2) (pos,neg) pair sum per class
// to power sums: T_k over all rows (T_0 = 1024 free), P_k over pos rows.
//
// R12 (R10 base, tail fused):
//   - 128 blocks x 128 threads; block c owns class c entirely (block-local,
//     no inter-block data exchange -- R7/R9/R11 all proved that loses).
//   - All 16 LDGs front-batched (MLP=16).
//   - Single packed 64-bit atomicAdd carries {block count, valid count,
//     fixed-point mean sum}: data + ticket + ordering in one op. No fence,
//     no reload; last arriver reconstructs the total from the return value.
//     Integer accumulation -> bit-exact across graph replays.

#define NROWS 1024
#define NCLS  128
#define NBLK  128
#define NTH   128
#define NW    (NTH / 32)     // 4 warps
#define RPT   (NROWS / NTH)  // 8 rows per thread
#define FXS   1099511627776.0   // 2^40 fixed-point scale

__device__ unsigned long long g_pack = 0ULL;

__global__ __launch_bounds__(NTH)
void aucm_kernel(const float* __restrict__ logits,
                 const float* __restrict__ targets,
                 float* __restrict__ out)
{
    const int c    = blockIdx.x;   // class
    const int tid  = threadIdx.x;
    const int warp = tid >> 5;
    const int lane = tid & 31;

    // Front-batched loads: 16 independent LDGs in flight.
    float xs[RPT], tg[RPT];
#pragma unroll
    for (int r = 0; r < RPT; r++) {
        const int row = tid + r * NTH;
        xs[r] = logits [row * NCLS + c];
        tg[r] = targets[row * NCLS + c];   // exact 0.0f / 1.0f
    }

    // Power sums: T_k = sum p^k over my rows (k=1..4), P_k over pos rows (k=0..4).
    float T1 = 0.f, T2 = 0.f, T3 = 0.f, T4 = 0.f;
    float P0 = 0.f, P1 = 0.f, P2 = 0.f, P3 = 0.f, P4 = 0.f;
#pragma unroll
    for (int r = 0; r < RPT; r++) {
        const float p  = __fdividef(1.0f, 1.0f + __expf(-xs[r]));
        const float p2 = p * p, p3 = p2 * p, p4 = p2 * p2;
        T1 += p; T2 += p2; T3 += p3; T4 += p4;
        const float t = tg[r];
        P0 += t;
        P1 = fmaf(t, p,  P1);
        P2 = fmaf(t, p2, P2);
        P3 = fmaf(t, p3, P3);
        P4 = fmaf(t, p4, P4);
    }

    // Warp tree reduction (9 accumulators).
#pragma unroll
    for (int off = 16; off > 0; off >>= 1) {
        T1 += __shfl_xor_sync(0xffffffffu, T1, off);
        T2 += __shfl_xor_sync(0xffffffffu, T2, off);
        T3 += __shfl_xor_sync(0xffffffffu, T3, off);
        T4 += __shfl_xor_sync(0xffffffffu, T4, off);
        P0 += __shfl_xor_sync(0xffffffffu, P0, off);
        P1 += __shfl_xor_sync(0xffffffffu, P1, off);
        P2 += __shfl_xor_sync(0xffffffffu, P2, off);
        P3 += __shfl_xor_sync(0xffffffffu, P3, off);
        P4 += __shfl_xor_sync(0xffffffffu, P4, off);
    }

    __shared__ float s[NW][9];
    if (lane == 0) {
        s[warp][0] = T1; s[warp][1] = T2; s[warp][2] = T3; s[warp][3] = T4;
        s[warp][4] = P0; s[warp][5] = P1; s[warp][6] = P2; s[warp][7] = P3;
        s[warp][8] = P4;
    }
    __syncthreads();
    if (tid != 0) return;

    // ---- thread 0: cross-warp sum (36 parallel LDS) + fp32 combine ----
    float m[9];
#pragma unroll
    for (int k = 0; k < 9; k++)
        m[k] = s[0][k] + s[1][k] + s[2][k] + s[3][k];

    const float Td0 = (float)NROWS;
    const float Td1 = m[0], Td2 = m[1], Td3 = m[2], Td4 = m[3];
    const float Pd0 = m[4], Pd1 = m[5], Pd2 = m[6], Pd3 = m[7], Pd4 = m[8];
    const float B0 = Td0 - Pd0, B1 = Td1 - Pd1, B2 = Td2 - Pd2,
                B3 = Td3 - Pd3, B4 = Td4 - Pd4;   // neg-row power sums

    const float cnt = Pd0 * B0;
    // d_m = sum_pairs (b-a)^m via binomial; Am_k = (-1)^k Pd_k.
    const float d1 = B1 * Pd0 - B0 * Pd1;
    const float d2 = B2 * Pd0 - 2.0f * B1 * Pd1 + B0 * Pd2;
    const float d4 = B4 * Pd0 - 4.0f * B3 * Pd1 + 6.0f * B2 * Pd2
                   - 4.0f * B1 * Pd3 + B0 * Pd4;

    const float S = 0.69314718f * cnt
                  + 0.5f * d1
                  + d2 * (1.0f / 8.0f)
                  - d4 * (1.0f / 192.0f);

    const bool ok = (cnt > 0.0f);
    const float mean = ok ? (S / cnt) : 0.0f;   // in (0, 1.32)

    // Packed contribution: [count:8][valid:8][mean fixed-point 2^40:48].
    const unsigned long long fx =
        (unsigned long long)((double)mean * FXS + 0.5);
    const unsigned long long pk =
        (1ULL << 56) | ((ok ? 1ULL : 0ULL) << 48) | fx;

    const unsigned long long old = atomicAdd(&g_pack, pk);
    if ((old >> 56) == (unsigned long long)(NBLK - 1)) {
        // Last arriver: total is in hand, no fence/reload needed.
        const unsigned long long tot = old + pk;
        const double sum = (double)(tot & ((1ULL << 48) - 1)) * (1.0 / FXS);
        const double vc  = (double)((tot >> 48) & 0xFFULL);
        out[0] = (vc > 0.0) ? (float)(sum / vc) : 0.0f;
        g_pack = 0ULL;   // reset for next graph replay (all blocks done)
    }
}

extern "C" void kernel_launch(void* const* d_in, const int* in_sizes, int n_in,
                              void* d_out, int out_size)
{
    const float* logits  = (const float*)d_in[0];
    const float* targets = (const float*)d_in[1];
    float* out = (float*)d_out;

    aucm_kernel<<<NBLK, NTH>>>(logits, targets, out);
}